// round 16
// baseline (speedup 1.0000x reference)
#include <cuda_runtime.h>
#include <cuda_bf16.h>
#include <cstdint>

#define SEQ   2048
#define BATCH 2
#define DM    1024
#define NH    16
#define DK    64
#define MROWS (BATCH * SEQ)                   // 4096
#define OUT_ELEMS ((size_t)BATCH * SEQ * DM)  // 4194304
#define NROWS_ATTN (BATCH * NH * SEQ)         // 65536

typedef __nv_bfloat16 bf16;

// -------- device scratch (alloc-free rule) --------
__device__ bf16 g_qhi[MROWS * DM], g_qlo[MROWS * DM];
__device__ bf16 g_khi[MROWS * DM], g_klo[MROWS * DM];
__device__ bf16 g_vhi[MROWS * DM], g_vlo[MROWS * DM];
__device__ bf16 g_wqhi[DM * DM],  g_wqlo[DM * DM];
__device__ bf16 g_wvhi[DM * DM],  g_wvlo[DM * DM];
__device__ bf16 g_wohi[DM * DM],  g_wolo[DM * DM];
__device__ bf16 g_Qhi[MROWS * DM], g_Qlo[MROWS * DM];
__device__ bf16 g_Khi[MROWS * DM], g_Klo[MROWS * DM];
__device__ bf16 g_Vthi[MROWS * DM], g_Vtlo[MROWS * DM];  // [b][dm_col][tok]
__device__ bf16 g_Chi[MROWS * DM], g_Clo[MROWS * DM];
__device__ float g_rowsum[NROWS_ATTN];

__device__ __forceinline__ void bsplit(float x, bf16& h, bf16& l)
{
    h = __float2bfloat16(x);
    l = __float2bfloat16(x - __bfloat162float(h));
}

// m16n8k16 BF16 MMA, D += A*B (row.col)
__device__ __forceinline__ void mma_bf16(float4& d,
    uint32_t a0, uint32_t a1, uint32_t a2, uint32_t a3, uint32_t b0, uint32_t b1)
{
    asm volatile(
        "mma.sync.aligned.m16n8k16.row.col.f32.bf16.bf16.f32 "
        "{%0,%1,%2,%3}, {%4,%5,%6,%7}, {%8,%9}, {%0,%1,%2,%3};\n"
        : "+f"(d.x), "+f"(d.y), "+f"(d.z), "+f"(d.w)
        : "r"(a0), "r"(a1), "r"(a2), "r"(a3), "r"(b0), "r"(b1));
}

// warp-collective: 4x m8n8 b16 matrices
__device__ __forceinline__ void ldsm_x4(uint32_t& r0, uint32_t& r1, uint32_t& r2, uint32_t& r3,
                                        uint32_t saddr)
{
    asm volatile("ldmatrix.sync.aligned.m8n8.x4.shared.b16 {%0,%1,%2,%3}, [%4];"
                 : "=r"(r0), "=r"(r1), "=r"(r2), "=r"(r3) : "r"(saddr));
}

__device__ __forceinline__ void cpa16(bf16* smem_dst, const bf16* gsrc)
{
    uint32_t sa = (uint32_t)__cvta_generic_to_shared(smem_dst);
    asm volatile("cp.async.cg.shared.global [%0], [%1], 16;\n" :: "r"(sa), "l"(gsrc));
}
__device__ __forceinline__ void cpa_commit() { asm volatile("cp.async.commit_group;\n"); }
__device__ __forceinline__ void cpa_wait1()  { asm volatile("cp.async.wait_group 1;\n"); }

// ---------------------------------------------------------------------------
__global__ __launch_bounds__(256) void zero_rowsum_kernel(float* __restrict__ rs)
{
    int i = blockIdx.x * 256 + threadIdx.x;
    if (i < NROWS_ATTN) rs[i] = 0.0f;
}

// ---------------------------------------------------------------------------
// Merged split: y=0..2 selects tensor.
// ---------------------------------------------------------------------------
__global__ __launch_bounds__(256) void split3_kernel(
    const float* __restrict__ x0, const float* __restrict__ x1, const float* __restrict__ x2,
    bf16* __restrict__ h0p, bf16* __restrict__ l0p,
    bf16* __restrict__ h1p, bf16* __restrict__ l1p,
    bf16* __restrict__ h2p, bf16* __restrict__ l2p, int n4)
{
    const float* x; bf16 *hi, *lo;
    if (blockIdx.y == 0)      { x = x0; hi = h0p; lo = l0p; }
    else if (blockIdx.y == 1) { x = x1; hi = h1p; lo = l1p; }
    else                      { x = x2; hi = h2p; lo = l2p; }
    int i = blockIdx.x * 256 + threadIdx.x;
    if (i >= n4) return;
    float4 v = ((const float4*)x)[i];
    bf16 h0, l0, h1, l1, h2, l2, h3, l3;
    bsplit(v.x, h0, l0); bsplit(v.y, h1, l1);
    bsplit(v.z, h2, l2); bsplit(v.w, h3, l3);
    ((__nv_bfloat162*)hi)[2 * i]     = __nv_bfloat162(h0, h1);
    ((__nv_bfloat162*)hi)[2 * i + 1] = __nv_bfloat162(h2, h3);
    ((__nv_bfloat162*)lo)[2 * i]     = __nv_bfloat162(l0, l1);
    ((__nv_bfloat162*)lo)[2 * i + 1] = __nv_bfloat162(l2, l3);
}

// ---------------------------------------------------------------------------
// 512-thread GEMM core, 2-stage cp.async pipeline, LDSM fragment loads.
// BK=64, stride 72 (144B rows: ldmatrix conflict-free).
// ---------------------------------------------------------------------------
#define PLANE  (128 * 72)
#define STAGE  (4 * PLANE)

struct GemmCtx {
    const bf16 *Ahi, *Alo, *Whi, *Wlo;
    int rowBase, colBase;
};

__device__ __forceinline__ void gemm_issue_stage(
    const GemmCtx& g, bf16* st, int k0, int t)
{
    #pragma unroll
    for (int i = 0; i < 2; i++) {
        int id = t + i * 512;
        int r = id >> 3, c8 = (id & 7) * 8;
        size_t aoff = (size_t)(g.rowBase + r) * DM + k0 + c8;
        size_t woff = (size_t)(g.colBase + r) * DM + k0 + c8;
        cpa16(&st[r * 72 + c8],             &g.Ahi[aoff]);
        cpa16(&st[PLANE + r * 72 + c8],     &g.Alo[aoff]);
        cpa16(&st[2 * PLANE + r * 72 + c8], &g.Whi[woff]);
        cpa16(&st[3 * PLANE + r * 72 + c8], &g.Wlo[woff]);
    }
}

__device__ __forceinline__ void gemm_core512(
    const GemmCtx& g, bf16* smg, int t, int wm, int wn, int gr, int gc,
    float4 acc[2][4])
{
    const int lane = t & 31;
    const int grp = lane >> 3, wr = lane & 7;
    int aoff[2], boff[2];
    #pragma unroll
    for (int mi = 0; mi < 2; mi++)
        aoff[mi] = (wm * 32 + mi * 16 + (grp & 1) * 8 + wr) * 72 + (grp >> 1) * 8;
    #pragma unroll
    for (int p = 0; p < 2; p++)
        boff[p] = (wn * 32 + p * 16 + (grp >> 1) * 8 + wr) * 72 + (grp & 1) * 8;

    const uint32_t smbase = (uint32_t)__cvta_generic_to_shared(smg);

    gemm_issue_stage(g, smg, 0, t);
    cpa_commit();

    for (int kt = 0; kt < 16; kt++) {
        const int cur = kt & 1;
        if (kt + 1 < 16)
            gemm_issue_stage(g, smg + (cur ^ 1) * STAGE, (kt + 1) * 64, t);
        cpa_commit();
        cpa_wait1();
        __syncthreads();

        const uint32_t sA  = smbase + cur * (STAGE * 2);
        const uint32_t sAl = sA + PLANE * 2;
        const uint32_t sB  = sA + 2 * (PLANE * 2);
        const uint32_t sBl = sA + 3 * (PLANE * 2);

        #pragma unroll
        for (int ks = 0; ks < 4; ks++) {
            const int kb = ks * 16;
            uint32_t ah[2][4], al[2][4], bhf[4][2], blf[4][2];
            #pragma unroll
            for (int mi = 0; mi < 2; mi++) {
                uint32_t ao = (uint32_t)(aoff[mi] + kb) * 2;
                ldsm_x4(ah[mi][0], ah[mi][1], ah[mi][2], ah[mi][3], sA + ao);
                ldsm_x4(al[mi][0], al[mi][1], al[mi][2], al[mi][3], sAl + ao);
            }
            #pragma unroll
            for (int p = 0; p < 2; p++) {
                uint32_t bo = (uint32_t)(boff[p] + kb) * 2;
                ldsm_x4(bhf[2 * p][0], bhf[2 * p][1], bhf[2 * p + 1][0], bhf[2 * p + 1][1], sB + bo);
                ldsm_x4(blf[2 * p][0], blf[2 * p][1], blf[2 * p + 1][0], blf[2 * p + 1][1], sBl + bo);
            }
            #pragma unroll
            for (int ni = 0; ni < 4; ni++)
                #pragma unroll
                for (int mi = 0; mi < 2; mi++) {
                    mma_bf16(acc[mi][ni], ah[mi][0], ah[mi][1], ah[mi][2], ah[mi][3], blf[ni][0], blf[ni][1]);
                    mma_bf16(acc[mi][ni], al[mi][0], al[mi][1], al[mi][2], al[mi][3], bhf[ni][0], bhf[ni][1]);
                    mma_bf16(acc[mi][ni], ah[mi][0], ah[mi][1], ah[mi][2], ah[mi][3], bhf[ni][0], bhf[ni][1]);
                }
        }
        __syncthreads();
    }
}

// ---------------------------------------------------------------------------
// Merged projection GEMM (512 threads): z=0 Q, z=1 K (W=wq), z=2 V (W=wv,
// transposed output planes).
// ---------------------------------------------------------------------------
__global__ __launch_bounds__(512) void proj_bf3(
    const bf16* __restrict__ qhi, const bf16* __restrict__ qlo,
    const bf16* __restrict__ khi, const bf16* __restrict__ klo,
    const bf16* __restrict__ vhi, const bf16* __restrict__ vlo,
    const bf16* __restrict__ wqhi, const bf16* __restrict__ wqlo,
    const bf16* __restrict__ wvhi, const bf16* __restrict__ wvlo,
    const float* __restrict__ b_q, const float* __restrict__ b_v,
    bf16* __restrict__ Qhi, bf16* __restrict__ Qlo,
    bf16* __restrict__ Khi, bf16* __restrict__ Klo,
    bf16* __restrict__ Vthi, bf16* __restrict__ Vtlo)
{
    extern __shared__ bf16 smg[];
    const int t = threadIdx.x, lane = t & 31, warp = t >> 5;
    const int wm = warp >> 2, wn = warp & 3;
    const int gr = lane >> 2, gc = lane & 3;
    const int z = blockIdx.z;

    GemmCtx g;
    const float* bias;
    bf16 *Chi, *Clo;
    bool transposed;
    if (z == 0)      { g.Ahi = qhi; g.Alo = qlo; g.Whi = wqhi; g.Wlo = wqlo; bias = b_q; Chi = Qhi;  Clo = Qlo;  transposed = false; }
    else if (z == 1) { g.Ahi = khi; g.Alo = klo; g.Whi = wqhi; g.Wlo = wqlo; bias = b_q; Chi = Khi;  Clo = Klo;  transposed = false; }
    else             { g.Ahi = vhi; g.Alo = vlo; g.Whi = wvhi; g.Wlo = wvlo; bias = b_v; Chi = Vthi; Clo = Vtlo; transposed = true;  }
    g.rowBase = blockIdx.y * 128;
    g.colBase = blockIdx.x * 128;

    float4 acc[2][4] = {};
    gemm_core512(g, smg, t, wm, wn, gr, gc, acc);

    #pragma unroll
    for (int mi = 0; mi < 2; mi++) {
        int r = g.rowBase + wm * 32 + mi * 16 + gr;
        #pragma unroll
        for (int ni = 0; ni < 4; ni++) {
            int c = g.colBase + wn * 32 + ni * 8 + 2 * gc;
            float bx = bias[c], by = bias[c + 1];
            float x0 = acc[mi][ni].x + bx, y0 = acc[mi][ni].y + by;
            float z0 = acc[mi][ni].z + bx, w0 = acc[mi][ni].w + by;
            if (!transposed) {
                bf16 h0, l0, h1, l1, h2, l2, h3, l3;
                bsplit(x0, h0, l0); bsplit(y0, h1, l1);
                bsplit(z0, h2, l2); bsplit(w0, h3, l3);
                *(__nv_bfloat162*)&Chi[(size_t)r * DM + c]       = __nv_bfloat162(h0, h1);
                *(__nv_bfloat162*)&Clo[(size_t)r * DM + c]       = __nv_bfloat162(l0, l1);
                *(__nv_bfloat162*)&Chi[(size_t)(r + 8) * DM + c] = __nv_bfloat162(h2, h3);
                *(__nv_bfloat162*)&Clo[(size_t)(r + 8) * DM + c] = __nv_bfloat162(l2, l3);
            } else {
                int bidx = r >> 11, tok = r & 2047;
                size_t base = ((size_t)bidx * DM + c) * SEQ + tok;
                bf16 h, l;
                bsplit(x0, h, l); Chi[base] = h;            Clo[base] = l;
                bsplit(y0, h, l); Chi[base + SEQ] = h;      Clo[base + SEQ] = l;
                bsplit(z0, h, l); Chi[base + 8] = h;        Clo[base + 8] = l;
                bsplit(w0, h, l); Chi[base + SEQ + 8] = h;  Clo[base + SEQ + 8] = l;
            }
        }
    }
}

// ---------------------------------------------------------------------------
// Output projection (512 threads): C = Ctx @ Wo^T + b_o -> f32.
// ---------------------------------------------------------------------------
__global__ __launch_bounds__(512) void outproj_bf3(
    const bf16* __restrict__ Ahi, const bf16* __restrict__ Alo,
    const bf16* __restrict__ Whi, const bf16* __restrict__ Wlo,
    const float* __restrict__ bias, float* __restrict__ Cf)
{
    extern __shared__ bf16 smg[];
    const int t = threadIdx.x, lane = t & 31, warp = t >> 5;
    const int wm = warp >> 2, wn = warp & 3;
    const int gr = lane >> 2, gc = lane & 3;

    GemmCtx g{Ahi, Alo, Whi, Wlo, (int)(blockIdx.y * 128), (int)(blockIdx.x * 128)};
    float4 acc[2][4] = {};
    gemm_core512(g, smg, t, wm, wn, gr, gc, acc);

    #pragma unroll
    for (int mi = 0; mi < 2; mi++) {
        int r = g.rowBase + wm * 32 + mi * 16 + gr;
        #pragma unroll
        for (int ni = 0; ni < 4; ni++) {
            int c = g.colBase + wn * 32 + ni * 8 + 2 * gc;
            float bx = bias[c], by = bias[c + 1];
            *(float2*)&Cf[(size_t)r * DM + c]       = make_float2(acc[mi][ni].x + bx, acc[mi][ni].y + by);
            *(float2*)&Cf[(size_t)(r + 8) * DM + c] = make_float2(acc[mi][ni].z + bx, acc[mi][ni].w + by);
        }
    }
}

// ---------------------------------------------------------------------------
// Stats (512 threads): QK^T -> e = exp(s*0.125) (0 where mask==0), per-row
// sums via atomicAdd. NO attn write (fused_npv recomputes).
// ---------------------------------------------------------------------------
__global__ __launch_bounds__(512) void attn_stats_bf(
    const bf16* __restrict__ Qhi, const bf16* __restrict__ Qlo,
    const bf16* __restrict__ Khi, const bf16* __restrict__ Klo,
    const int* __restrict__ mask, float* __restrict__ rowsum)
{
    extern __shared__ bf16 sms[];
    bf16* sQhi = sms;                // 128 x 72
    bf16* sQlo = sQhi + 128 * 72;
    bf16* sKhi = sQlo + 128 * 72;
    bf16* sKlo = sKhi + 128 * 72;
    __shared__ float pm[4 * 128];

    const int t = threadIdx.x, lane = t & 31, warp = t >> 5;
    const int wm = warp >> 2, wn = warp & 3;
    const int gr = lane >> 2, gc = lane & 3;
    const int grp = lane >> 3, wr = lane & 7;
    const int bh = blockIdx.z;
    const int b = bh >> 4, h = bh & 15;
    const int qBase = blockIdx.y * 128;
    const int kBase = blockIdx.x * 128;

    #pragma unroll
    for (int i = 0; i < 2; i++) {
        int id = t + i * 512;
        int r = id >> 3, c = id & 7;
        size_t qoff = (size_t)(b * SEQ + qBase + r) * DM + h * DK + c * 8;
        size_t koff = (size_t)(b * SEQ + kBase + r) * DM + h * DK + c * 8;
        *(float4*)&sQhi[r * 72 + c * 8] = *(const float4*)&Qhi[qoff];
        *(float4*)&sQlo[r * 72 + c * 8] = *(const float4*)&Qlo[qoff];
        *(float4*)&sKhi[r * 72 + c * 8] = *(const float4*)&Khi[koff];
        *(float4*)&sKlo[r * 72 + c * 8] = *(const float4*)&Klo[koff];
    }
    __syncthreads();

    const uint32_t sQ  = (uint32_t)__cvta_generic_to_shared(sQhi);
    const uint32_t sQl = sQ + PLANE * 2;
    const uint32_t sK  = sQ + 2 * (PLANE * 2);
    const uint32_t sKl = sQ + 3 * (PLANE * 2);
    int aoff[2], boff[2];
    #pragma unroll
    for (int mi = 0; mi < 2; mi++)
        aoff[mi] = (wm * 32 + mi * 16 + (grp & 1) * 8 + wr) * 72 + (grp >> 1) * 8;
    #pragma unroll
    for (int p = 0; p < 2; p++)
        boff[p] = (wn * 32 + p * 16 + (grp >> 1) * 8 + wr) * 72 + (grp & 1) * 8;

    float4 acc[2][4] = {};
    #pragma unroll
    for (int ks = 0; ks < 4; ks++) {
        const int kb = ks * 16;
        uint32_t ah[2][4], al[2][4], bhf[4][2], blf[4][2];
        #pragma unroll
        for (int mi = 0; mi < 2; mi++) {
            uint32_t ao = (uint32_t)(aoff[mi] + kb) * 2;
            ldsm_x4(ah[mi][0], ah[mi][1], ah[mi][2], ah[mi][3], sQ + ao);
            ldsm_x4(al[mi][0], al[mi][1], al[mi][2], al[mi][3], sQl + ao);
        }
        #pragma unroll
        for (int p = 0; p < 2; p++) {
            uint32_t bo = (uint32_t)(boff[p] + kb) * 2;
            ldsm_x4(bhf[2 * p][0], bhf[2 * p][1], bhf[2 * p + 1][0], bhf[2 * p + 1][1], sK + bo);
            ldsm_x4(blf[2 * p][0], blf[2 * p][1], blf[2 * p + 1][0], blf[2 * p + 1][1], sKl + bo);
        }
        #pragma unroll
        for (int ni = 0; ni < 4; ni++)
            #pragma unroll
            for (int mi = 0; mi < 2; mi++) {
                mma_bf16(acc[mi][ni], ah[mi][0], ah[mi][1], ah[mi][2], ah[mi][3], blf[ni][0], blf[ni][1]);
                mma_bf16(acc[mi][ni], al[mi][0], al[mi][1], al[mi][2], al[mi][3], bhf[ni][0], bhf[ni][1]);
                mma_bf16(acc[mi][ni], ah[mi][0], ah[mi][1], ah[mi][2], ah[mi][3], bhf[ni][0], bhf[ni][1]);
            }
    }

    const float scale = 0.125f;
    float es[2][2] = {};
    #pragma unroll
    for (int mi = 0; mi < 2; mi++) {
        #pragma unroll
        for (int ni = 0; ni < 4; ni++) {
            int c = kBase + wn * 32 + ni * 8 + 2 * gc;
            int m0 = mask[b * SEQ + c], m1 = mask[b * SEQ + c + 1];
            float ex = m0 ? __expf(acc[mi][ni].x * scale) : 0.0f;
            float ey = m1 ? __expf(acc[mi][ni].y * scale) : 0.0f;
            float ez = m0 ? __expf(acc[mi][ni].z * scale) : 0.0f;
            float ew = m1 ? __expf(acc[mi][ni].w * scale) : 0.0f;
            es[mi][0] += ex + ey;
            es[mi][1] += ez + ew;
        }
    }

    #pragma unroll
    for (int o = 1; o <= 2; o <<= 1)
        #pragma unroll
        for (int mi = 0; mi < 2; mi++)
            #pragma unroll
            for (int hf = 0; hf < 2; hf++)
                es[mi][hf] += __shfl_xor_sync(0xffffffffu, es[mi][hf], o);
    if (gc == 0) {
        #pragma unroll
        for (int mi = 0; mi < 2; mi++)
            #pragma unroll
            for (int hf = 0; hf < 2; hf++) {
                int row = wm * 32 + mi * 16 + hf * 8 + gr;
                pm[wn * 128 + row] = es[mi][hf];
            }
    }
    __syncthreads();
    if (t < 128) {
        float s = pm[t] + pm[128 + t] + pm[256 + t] + pm[384 + t];
        atomicAdd(&rowsum[(size_t)bh * SEQ + qBase + t], s);
    }
}

// ---------------------------------------------------------------------------
// Fused normalize + PV with QK recompute (512 threads, grid (qt, bh)).
// Per ktile: K,V tiles -> QK MMA -> p = exp(s/8)*inv (masked) -> write attn
// once -> stage p hi/lo in smem -> PV 3-MMA into ctx accumulators.
// ---------------------------------------------------------------------------
__global__ __launch_bounds__(512) void fused_npv(
    const bf16* __restrict__ Qhi, const bf16* __restrict__ Qlo,
    const bf16* __restrict__ Khi, const bf16* __restrict__ Klo,
    const int* __restrict__ mask, const float* __restrict__ rowsum,
    float* __restrict__ attn,
    const bf16* __restrict__ Vthi, const bf16* __restrict__ Vtlo,
    bf16* __restrict__ Chi, bf16* __restrict__ Clo)
{
    extern __shared__ unsigned char smraw[];
    float* sm_inv = (float*)smraw;                 // 128
    int*   smask  = (int*)(sm_inv + 128);          // 2048
    bf16* sQhi = (bf16*)(smask + 2048);            // 128 x 72
    bf16* sQlo = sQhi + 128 * 72;
    bf16* sKhi = sQlo + 128 * 72;                  // 128 x 72
    bf16* sKlo = sKhi + 128 * 72;
    bf16* sPhi = sKlo + 128 * 72;                  // 128 x 136
    bf16* sPlo = sPhi + 128 * 136;
    bf16* sVhi = sPlo + 128 * 136;                 // 64 x 136
    bf16* sVlo = sVhi + 64 * 136;

    const int t = threadIdx.x, lane = t & 31, warp = t >> 5;
    const int wm = warp >> 2, wn = warp & 3;
    const int gr = lane >> 2, gc = lane & 3;
    const int grp = lane >> 3, wr = lane & 7;
    const int qBase = blockIdx.x * 128;
    const int bh = blockIdx.y;
    const int b = bh >> 4, h = bh & 15;
    const float scale = 0.125f;

    // inv + mask + Q strip
    if (t < 128)
        sm_inv[t] = 1.0f / rowsum[(size_t)bh * SEQ + qBase + t];
    for (int i = t; i < SEQ; i += 512) smask[i] = mask[b * SEQ + i];
    #pragma unroll
    for (int i = 0; i < 2; i++) {
        int id = t + i * 512;
        int r = id >> 3, c = id & 7;
        size_t qoff = (size_t)(b * SEQ + qBase + r) * DM + h * DK + c * 8;
        *(float4*)&sQhi[r * 72 + c * 8] = *(const float4*)&Qhi[qoff];
        *(float4*)&sQlo[r * 72 + c * 8] = *(const float4*)&Qlo[qoff];
    }
    __syncthreads();

    // fragment addresses
    const uint32_t aQ  = (uint32_t)__cvta_generic_to_shared(sQhi);
    const uint32_t aQl = (uint32_t)__cvta_generic_to_shared(sQlo);
    const uint32_t aK  = (uint32_t)__cvta_generic_to_shared(sKhi);
    const uint32_t aKl = (uint32_t)__cvta_generic_to_shared(sKlo);
    const uint32_t aP  = (uint32_t)__cvta_generic_to_shared(sPhi);
    const uint32_t aPl = (uint32_t)__cvta_generic_to_shared(sPlo);
    const uint32_t aV  = (uint32_t)__cvta_generic_to_shared(sVhi);
    const uint32_t aVl = (uint32_t)__cvta_generic_to_shared(sVlo);
    int aoff[2], boff[2], poff[2], voff;
    #pragma unroll
    for (int mi = 0; mi < 2; mi++) {
        aoff[mi] = (wm * 32 + mi * 16 + (grp & 1) * 8 + wr) * 72 + (grp >> 1) * 8;
        poff[mi] = (wm * 32 + mi * 16 + (grp & 1) * 8 + wr) * 136 + (grp >> 1) * 8;
    }
    #pragma unroll
    for (int p = 0; p < 2; p++)
        boff[p] = (wn * 32 + p * 16 + (grp >> 1) * 8 + wr) * 72 + (grp & 1) * 8;
    voff = (wn * 16 + (grp >> 1) * 8 + wr) * 136 + (grp & 1) * 8;

    float4 ctx[2][2] = {};

    for (int kt = 0; kt < 16; kt++) {
        // load K tile (128x64 per plane) + V tile (64 d x 128 tok)
        #pragma unroll
        for (int i = 0; i < 2; i++) {
            int id = t + i * 512;
            int r = id >> 3, c = id & 7;
            size_t koff = (size_t)(b * SEQ + kt * 128 + r) * DM + h * DK + c * 8;
            *(float4*)&sKhi[r * 72 + c * 8] = *(const float4*)&Khi[koff];
            *(float4*)&sKlo[r * 72 + c * 8] = *(const float4*)&Klo[koff];
        }
        #pragma unroll
        for (int i = 0; i < 2; i++) {
            int id = t + i * 512;
            int d = id >> 4, c = id & 15;
            size_t off = ((size_t)b * DM + h * DK + d) * SEQ + kt * 128 + c * 8;
            *(float4*)&sVhi[d * 136 + c * 8] = *(const float4*)&Vthi[off];
            *(float4*)&sVlo[d * 136 + c * 8] = *(const float4*)&Vtlo[off];
        }
        __syncthreads();

        // --- QK MMA (warp tile 32x32) ---
        float4 acc[2][4] = {};
        #pragma unroll
        for (int ks = 0; ks < 4; ks++) {
            const int kb = ks * 16;
            uint32_t ah[2][4], al[2][4], bhf[4][2], blf[4][2];
            #pragma unroll
            for (int mi = 0; mi < 2; mi++) {
                uint32_t ao = (uint32_t)(aoff[mi] + kb) * 2;
                ldsm_x4(ah[mi][0], ah[mi][1], ah[mi][2], ah[mi][3], aQ + ao);
                ldsm_x4(al[mi][0], al[mi][1], al[mi][2], al[mi][3], aQl + ao);
            }
            #pragma unroll
            for (int p = 0; p < 2; p++) {
                uint32_t bo = (uint32_t)(boff[p] + kb) * 2;
                ldsm_x4(bhf[2 * p][0], bhf[2 * p][1], bhf[2 * p + 1][0], bhf[2 * p + 1][1], aK + bo);
                ldsm_x4(blf[2 * p][0], blf[2 * p][1], blf[2 * p + 1][0], blf[2 * p + 1][1], aKl + bo);
            }
            #pragma unroll
            for (int ni = 0; ni < 4; ni++)
                #pragma unroll
                for (int mi = 0; mi < 2; mi++) {
                    mma_bf16(acc[mi][ni], ah[mi][0], ah[mi][1], ah[mi][2], ah[mi][3], blf[ni][0], blf[ni][1]);
                    mma_bf16(acc[mi][ni], al[mi][0], al[mi][1], al[mi][2], al[mi][3], bhf[ni][0], bhf[ni][1]);
                    mma_bf16(acc[mi][ni], ah[mi][0], ah[mi][1], ah[mi][2], ah[mi][3], bhf[ni][0], bhf[ni][1]);
                }
        }

        // --- normalize + write final attn + stage P split ---
        #pragma unroll
        for (int mi = 0; mi < 2; mi++) {
            int lr = wm * 32 + mi * 16 + gr;
            float inv0 = sm_inv[lr], inv1 = sm_inv[lr + 8];
            size_t row0 = ((size_t)bh * SEQ + qBase + lr) * SEQ;
            size_t row1 = row0 + (size_t)8 * SEQ;
            #pragma unroll
            for (int ni = 0; ni < 4; ni++) {
                int cl = wn * 32 + ni * 8 + 2 * gc;
                int c = kt * 128 + cl;
                int m0 = smask[c], m1 = smask[c + 1];
                float px = m0 ? __expf(acc[mi][ni].x * scale) * inv0 : 0.0f;
                float py = m1 ? __expf(acc[mi][ni].y * scale) * inv0 : 0.0f;
                float pz = m0 ? __expf(acc[mi][ni].z * scale) * inv1 : 0.0f;
                float pw = m1 ? __expf(acc[mi][ni].w * scale) * inv1 : 0.0f;
                *(float2*)&attn[row0 + c] = make_float2(px, py);
                *(float2*)&attn[row1 + c] = make_float2(pz, pw);
                bf16 h0, l0, h1, l1;
                bsplit(px, h0, l0); bsplit(py, h1, l1);
                *(__nv_bfloat162*)&sPhi[lr * 136 + cl] = __nv_bfloat162(h0, h1);
                *(__nv_bfloat162*)&sPlo[lr * 136 + cl] = __nv_bfloat162(l0, l1);
                bsplit(pz, h0, l0); bsplit(pw, h1, l1);
                *(__nv_bfloat162*)&sPhi[(lr + 8) * 136 + cl] = __nv_bfloat162(h0, h1);
                *(__nv_bfloat162*)&sPlo[(lr + 8) * 136 + cl] = __nv_bfloat162(l0, l1);
            }
        }
        __syncthreads();

        // --- PV MMA (warp tile 32x16, full local k=128) ---
        #pragma unroll
        for (int ks = 0; ks < 8; ks++) {
            const int kb = ks * 16;
            uint32_t ah[2][4], al[2][4], bhf[2][2], blf[2][2];
            #pragma unroll
            for (int mi = 0; mi < 2; mi++) {
                uint32_t ao = (uint32_t)(poff[mi] + kb) * 2;
                ldsm_x4(ah[mi][0], ah[mi][1], ah[mi][2], ah[mi][3], aP + ao);
                ldsm_x4(al[mi][0], al[mi][1], al[mi][2], al[mi][3], aPl + ao);
            }
            {
                uint32_t bo = (uint32_t)(voff + kb) * 2;
                ldsm_x4(bhf[0][0], bhf[0][1], bhf[1][0], bhf[1][1], aV + bo);
                ldsm_x4(blf[0][0], blf[0][1], blf[1][0], blf[1][1], aVl + bo);
            }
            #pragma unroll
            for (int ni = 0; ni < 2; ni++)
                #pragma unroll
                for (int mi = 0; mi < 2; mi++) {
                    mma_bf16(ctx[mi][ni], ah[mi][0], ah[mi][1], ah[mi][2], ah[mi][3], blf[ni][0], blf[ni][1]);
                    mma_bf16(ctx[mi][ni], al[mi][0], al[mi][1], al[mi][2], al[mi][3], bhf[ni][0], bhf[ni][1]);
                    mma_bf16(ctx[mi][ni], ah[mi][0], ah[mi][1], ah[mi][2], ah[mi][3], bhf[ni][0], bhf[ni][1]);
                }
        }
        __syncthreads();
    }

    // ctx epilogue -> Chi/Clo planes [token][DM]
    #pragma unroll
    for (int mi = 0; mi < 2; mi++) {
        int q = qBase + wm * 32 + mi * 16 + gr;
        #pragma unroll
        for (int ni = 0; ni < 2; ni++) {
            int d = wn * 16 + ni * 8 + 2 * gc;
            size_t o0 = (size_t)(b * SEQ + q) * DM + h * DK + d;
            size_t o1 = o0 + (size_t)8 * DM;
            bf16 h0, l0, h1, l1;
            bsplit(ctx[mi][ni].x, h0, l0); bsplit(ctx[mi][ni].y, h1, l1);
            *(__nv_bfloat162*)&Chi[o0] = __nv_bfloat162(h0, h1);
            *(__nv_bfloat162*)&Clo[o0] = __nv_bfloat162(l0, l1);
            bsplit(ctx[mi][ni].z, h0, l0); bsplit(ctx[mi][ni].w, h1, l1);
            *(__nv_bfloat162*)&Chi[o1] = __nv_bfloat162(h0, h1);
            *(__nv_bfloat162*)&Clo[o1] = __nv_bfloat162(l0, l1);
        }
    }
}

// ---------------------------------------------------------------------------
extern "C" void kernel_launch(void* const* d_in, const int* in_sizes, int n_in,
                              void* d_out, int out_size)
{
    const float* q    = (const float*)d_in[0];
    const float* k    = (const float*)d_in[1];
    const float* v    = (const float*)d_in[2];
    const int*   mask = (const int*)d_in[3];
    const float* w_q  = (const float*)d_in[4];
    const float* b_q  = (const float*)d_in[5];
    const float* w_v  = (const float*)d_in[6];
    const float* b_v  = (const float*)d_in[7];
    const float* w_o  = (const float*)d_in[8];
    const float* b_o  = (const float*)d_in[9];

    float* out  = (float*)d_out;
    float* attn = out + OUT_ELEMS;

    bf16 *qhi, *qlo, *khi, *klo, *vhi, *vlo;
    bf16 *wqhi, *wqlo, *wvhi, *wvlo, *wohi, *wolo;
    bf16 *Qhi, *Qlo, *Khi, *Klo, *Vthi, *Vtlo, *Chi, *Clo;
    float* rsum;
    cudaGetSymbolAddress((void**)&qhi, g_qhi);   cudaGetSymbolAddress((void**)&qlo, g_qlo);
    cudaGetSymbolAddress((void**)&khi, g_khi);   cudaGetSymbolAddress((void**)&klo, g_klo);
    cudaGetSymbolAddress((void**)&vhi, g_vhi);   cudaGetSymbolAddress((void**)&vlo, g_vlo);
    cudaGetSymbolAddress((void**)&wqhi, g_wqhi); cudaGetSymbolAddress((void**)&wqlo, g_wqlo);
    cudaGetSymbolAddress((void**)&wvhi, g_wvhi); cudaGetSymbolAddress((void**)&wvlo, g_wvlo);
    cudaGetSymbolAddress((void**)&wohi, g_wohi); cudaGetSymbolAddress((void**)&wolo, g_wolo);
    cudaGetSymbolAddress((void**)&Qhi, g_Qhi);   cudaGetSymbolAddress((void**)&Qlo, g_Qlo);
    cudaGetSymbolAddress((void**)&Khi, g_Khi);   cudaGetSymbolAddress((void**)&Klo, g_Klo);
    cudaGetSymbolAddress((void**)&Vthi, g_Vthi); cudaGetSymbolAddress((void**)&Vtlo, g_Vtlo);
    cudaGetSymbolAddress((void**)&Chi, g_Chi);   cudaGetSymbolAddress((void**)&Clo, g_Clo);
    cudaGetSymbolAddress((void**)&rsum, g_rowsum);

    const int pipe_smem   = 2 * STAGE * 2;      // 147456 (2-stage cp.async)
    const int stats_smem  = 4 * 128 * 72 * 2;   // 73728
    const int fused_smem  = 128 * 4 + 2048 * 4 +
                            (2 * 128 * 72 + 2 * 128 * 72 + 2 * 128 * 136 + 2 * 64 * 136) * 2;

    static bool attr_set = false;
    if (!attr_set) {
        cudaFuncSetAttribute(proj_bf3, cudaFuncAttributeMaxDynamicSharedMemorySize, pipe_smem);
        cudaFuncSetAttribute(outproj_bf3, cudaFuncAttributeMaxDynamicSharedMemorySize, pipe_smem);
        cudaFuncSetAttribute(attn_stats_bf, cudaFuncAttributeMaxDynamicSharedMemorySize, stats_smem);
        cudaFuncSetAttribute(fused_npv, cudaFuncAttributeMaxDynamicSharedMemorySize, fused_smem);
        attr_set = true;
    }

    // 0) zero row sums (graph-replay safe)
    zero_rowsum_kernel<<<(NROWS_ATTN + 255) / 256, 256>>>(rsum);

    // 1) splits
    {
        dim3 gIn((MROWS * DM / 4 + 255) / 256, 3);
        split3_kernel<<<gIn, 256>>>(q, k, v, qhi, qlo, khi, klo, vhi, vlo, MROWS * DM / 4);
        dim3 gW((DM * DM / 4 + 255) / 256, 3);
        split3_kernel<<<gW, 256>>>(w_q, w_v, w_o, wqhi, wqlo, wvhi, wvlo, wohi, wolo, DM * DM / 4);
    }

    // 2) merged projections
    dim3 gProj(DM / 128, MROWS / 128, 3);   // (8, 32, 3)
    proj_bf3<<<gProj, 512, pipe_smem>>>(qhi, qlo, khi, klo, vhi, vlo,
                                        wqhi, wqlo, wvhi, wvlo, b_q, b_v,
                                        Qhi, Qlo, Khi, Klo, Vthi, Vtlo);

    // 3) stats: row sums of e (no attn write)
    dim3 gScore(SEQ / 128, SEQ / 128, BATCH * NH);   // (16, 16, 32)
    attn_stats_bf<<<gScore, 512, stats_smem>>>(Qhi, Qlo, Khi, Klo, mask, rsum);

    // 4) fused: QK recompute + normalize + single attn write + PV
    dim3 gFused(SEQ / 128, BATCH * NH);              // (16, 32)
    fused_npv<<<gFused, 512, fused_smem>>>(Qhi, Qlo, Khi, Klo, mask, rsum, attn,
                                           Vthi, Vtlo, Chi, Clo);

    // 5) output projection -> f32 out
    dim3 gOut(DM / 128, MROWS / 128);
    outproj_bf3<<<gOut, 512, pipe_smem>>>(Chi, Clo, wohi, wolo, b_o, out);
}